// round 15
// baseline (speedup 1.0000x reference)
#include <cuda_runtime.h>
#include <cuda_bf16.h>
#include <cstdint>
#include <math.h>

// ---------------------------------------------------------------------------
// Binarized CNN (XNOR-net) forward pass. Bit-packed XNOR-popcount convs.
// R14: popc reduction moved to the fma pipe via inline mad.lo.s32 chains
//      (alu pipe was the 78%-busy bottleneck; fma was 6.5%). The x2 scale,
//      mode sign and base (V/K/part) fold into the mad weights/accumulator
//      start, deleting ~12 alu ops per dot. Otherwise identical to R13:
//      all passes CW=4 (36-reg patch), L2 CSA, integer thresholds, splits
//      via exact int partials. Bit-identical integer math.
// ---------------------------------------------------------------------------

#define NB 128

// Scratch (device globals; no allocation allowed)
__device__ uint32_t g_bits1[NB * 32 * 32 * 4];
__device__ uint32_t g_bits2[NB * 16 * 16 * 4];
__device__ uint32_t g_bits3[NB * 16 * 16 * 8];
__device__ uint32_t g_bits4[NB * 8 * 8 * 8];
__device__ uint32_t g_bits5[NB * 8 * 8 * 16];
__device__ float    g_h6[NB * 4 * 4 * 512];
__device__ int      g_part[NB * 16 * 16 * 256];     // partial dots (33.5MB max)
__device__ uint32_t g_wb2[9 * 4 * 128];
__device__ uint32_t g_wb3[9 * 4 * 256];
__device__ uint32_t g_wb4[9 * 8 * 256];
__device__ uint32_t g_wb5[9 * 8 * 512];
__device__ uint32_t g_wb6[9 * 16 * 512];
// Tables (per edge pattern x cout): V = K + C0 - T (threshold), K = edge corr.
__device__ int g_V2[9 * 128];
__device__ int g_V3[9 * 256];
__device__ int g_K4A[9 * 256];
__device__ int g_V4B[9 * 256];
__device__ int g_K5A[9 * 512];
__device__ int g_V5B[9 * 512];
__device__ int g_K6A[9 * 512];
__device__ int g_K6B[9 * 512];
__device__ int g_K6C[9 * 512];
__device__ int g_K6D[9 * 512];

// ---------------------------------------------------------------------------
// Weight-sign packing. Layout per layer: [tap(9)][cin_word][cout].
// ---------------------------------------------------------------------------
__device__ __forceinline__ void pack_one(const float* __restrict__ w,
                                         uint32_t* __restrict__ wb,
                                         int idx, int CIN, int COUT) {
    int cout = idx % COUT;
    int tw = idx / COUT;
    int cw = CIN >> 5;
    int wword = tw % cw;
    int tap = tw / cw;
    uint32_t m = 0;
#pragma unroll 8
    for (int j = 0; j < 32; j++) {
        float f = w[(tap * CIN + wword * 32 + j) * COUT + cout];
        m |= (f > 0.0f ? 1u : 0u) << j;
    }
    wb[idx] = m;
}

__global__ void pack_all_kernel(const float* __restrict__ w2, const float* __restrict__ w3,
                                const float* __restrict__ w4, const float* __restrict__ w5,
                                const float* __restrict__ w6,
                                uint32_t* __restrict__ wb2, uint32_t* __restrict__ wb3,
                                uint32_t* __restrict__ wb4, uint32_t* __restrict__ wb5,
                                uint32_t* __restrict__ wb6) {
    int idx = blockIdx.x * blockDim.x + threadIdx.x;
    const int n2 = 9 * 4 * 128, n3 = 9 * 4 * 256, n4 = 9 * 8 * 256,
              n5 = 9 * 8 * 512, n6 = 9 * 16 * 512;
    if (idx < n2) { pack_one(w2, wb2, idx, 128, 128); return; }
    idx -= n2;
    if (idx < n3) { pack_one(w3, wb3, idx, 128, 256); return; }
    idx -= n3;
    if (idx < n4) { pack_one(w4, wb4, idx, 256, 256); return; }
    idx -= n4;
    if (idx < n5) { pack_one(w5, wb5, idx, 256, 512); return; }
    idx -= n5;
    if (idx < n6) { pack_one(w6, wb6, idx, 512, 512); return; }
}

// ---------------------------------------------------------------------------
// K = (valid - 9)*CW*32 + 2 * sum_{invalid taps} popc(w_chunk)
// so that dot_true = C0 - 2*S_zeropadded + K, C0 = 9*CW*32.
// ---------------------------------------------------------------------------
__device__ __forceinline__ int k_compute(const uint32_t* __restrict__ wb,
                                         int c, int p, int CINW, int CW, int w0, int COUT) {
    int ty = p / 3, tx = p % 3;
    int sinv = 0, valid = 0;
    for (int ky = 0; ky < 3; ky++) {
        for (int kx = 0; kx < 3; kx++) {
            bool inv = (ty == 0 && ky == 0) || (ty == 2 && ky == 2) ||
                       (tx == 0 && kx == 0) || (tx == 2 && kx == 2);
            if (!inv) { valid++; continue; }
            for (int w = 0; w < CW; w++)
                sinv += __popc(wb[((size_t)(ky * 3 + kx) * CINW + w0 + w) * COUT + c]);
        }
    }
    return (valid - 9) * CW * 32 + 2 * sinv;
}

// V = K + C0 - T; T = max{ m : fmaf(m,sc,bi) <= 0 } (exact, same fmaf as the
// runtime predicate). bias>0 => relu makes the bit always 1 => big sentinel
// (all |z| quantities < 1e4, so 1e5 guarantees z<0).
__device__ __forceinline__ void v_one(const uint32_t* __restrict__ wb, int* __restrict__ V,
                                      int idx, int CINW, int CW, int w0, int COUT,
                                      const float* __restrict__ scale,
                                      const float* __restrict__ bias) {
    int c = idx % COUT;
    int p = idx / COUT;
    int K = k_compute(wb, c, p, CINW, CW, w0, COUT);
    const int C0 = 9 * CW * 32;
    float sc = scale[c], bi = bias[c];
    int v;
    if (bi > 0.0f) {
        v = 100000;
    } else {
        float t0 = -bi / sc;
        int T = (int)floorf(t0);
        while (fmaf((float)(T + 1), sc, bi) <= 0.0f) T++;
        while (fmaf((float)T, sc, bi) > 0.0f) T--;
        v = K + C0 - T;
    }
    V[idx] = v;
}

__device__ __forceinline__ void k_one(const uint32_t* __restrict__ wb, int* __restrict__ K,
                                      int idx, int CINW, int CW, int w0, int COUT) {
    int c = idx % COUT;
    int p = idx / COUT;
    K[idx] = k_compute(wb, c, p, CINW, CW, w0, COUT);
}

__global__ void tab_all_kernel(const uint32_t* __restrict__ wb2, const uint32_t* __restrict__ wb3,
                               const uint32_t* __restrict__ wb4, const uint32_t* __restrict__ wb5,
                               const uint32_t* __restrict__ wb6,
                               const float* s2, const float* b2, const float* s3, const float* b3,
                               const float* s4, const float* b4, const float* s5, const float* b5,
                               int* V2, int* V3, int* K4A, int* V4B, int* K5A, int* V5B,
                               int* K6A, int* K6B, int* K6C, int* K6D) {
    int idx = blockIdx.x * blockDim.x + threadIdx.x;
    const int t128 = 9 * 128, t256 = 9 * 256, t512 = 9 * 512;
    if (idx < t128) { v_one(wb2, V2, idx, 4, 4, 0, 128, s2, b2); return; }
    idx -= t128;
    if (idx < t256) { v_one(wb3, V3, idx, 4, 4, 0, 256, s3, b3); return; }
    idx -= t256;
    if (idx < t256) { k_one(wb4, K4A, idx, 8, 4, 0, 256); return; }
    idx -= t256;
    if (idx < t256) { v_one(wb4, V4B, idx, 8, 4, 4, 256, s4, b4); return; }
    idx -= t256;
    if (idx < t512) { k_one(wb5, K5A, idx, 8, 4, 0, 512); return; }
    idx -= t512;
    if (idx < t512) { v_one(wb5, V5B, idx, 8, 4, 4, 512, s5, b5); return; }
    idx -= t512;
    if (idx < t512) { k_one(wb6, K6A, idx, 16, 4, 0, 512); return; }
    idx -= t512;
    if (idx < t512) { k_one(wb6, K6B, idx, 16, 4, 4, 512); return; }
    idx -= t512;
    if (idx < t512) { k_one(wb6, K6C, idx, 16, 4, 8, 512); return; }
    idx -= t512;
    if (idx < t512) { k_one(wb6, K6D, idx, 16, 4, 12, 512); return; }
}

// ---------------------------------------------------------------------------
// conv1: float 3x3 SAME conv (3->128) + bias + relu + bn + binarize + pack.
// 8 consecutive pixels per block; 27 weights register-resident.
// ---------------------------------------------------------------------------
__global__ void __launch_bounds__(128) conv1_kernel(
    const float* __restrict__ x, const float* __restrict__ w1,
    const float* __restrict__ b1, const float* __restrict__ s1,
    const float* __restrict__ bb1, uint32_t* __restrict__ obits) {
    constexpr int PIX = 8;
    const int co = threadIdx.x;

    float wreg[27];
#pragma unroll
    for (int t = 0; t < 27; t++) wreg[t] = __ldg(w1 + t * 128 + co);
    const float bb = __ldg(b1 + co);
    const float sc = __ldg(s1 + co);
    const float bi = __ldg(bb1 + co);

    const int p0 = blockIdx.x * PIX;        // 8 consecutive x in one row
    const int y = (p0 >> 5) & 31;
    const int n = p0 >> 10;
    const int x0 = p0 & 31;

#pragma unroll 1
    for (int pp = 0; pp < PIX; pp++) {
        int xx = x0 + pp;
        float acc = 0.0f;
#pragma unroll
        for (int ky = 0; ky < 3; ky++) {
            int iy = y + ky - 1;
            if ((unsigned)iy >= 32u) continue;
#pragma unroll
            for (int kx = 0; kx < 3; kx++) {
                int ix = xx + kx - 1;
                if ((unsigned)ix >= 32u) continue;
                const float* xp = x + ((n * 32 + iy) * 32 + ix) * 3;
                const float* wr = wreg + (ky * 3 + kx) * 3;
                acc = fmaf(xp[0], wr[0], acc);
                acc = fmaf(xp[1], wr[1], acc);
                acc = fmaf(xp[2], wr[2], acc);
            }
        }
        float v = fmaxf(acc + bb, 0.0f);
        v = fmaf(v, sc, bi);
        unsigned mask = __ballot_sync(0xffffffffu, v > 0.0f);
        if ((co & 31) == 0) obits[(p0 + pp) * 4 + (co >> 5)] = mask;
    }
}

// Full adder (carry-save): s = xor3 (LOP3 0x96), c = majority (LOP3 0xE8).
__device__ __forceinline__ void csa(uint32_t a, uint32_t b, uint32_t d,
                                    uint32_t& s, uint32_t& c) {
    s = a ^ b ^ d;
    c = (a & b) | (d & (a ^ b));
}

// Integer mad pinned to IMAD (fma pipe) — keeps the popc reduction off the
// saturated alu pipe.
__device__ __forceinline__ int madi(int a, int b, int c) {
    int d;
    asm("mad.lo.s32 %0, %1, %2, %3;" : "=r"(d) : "r"(a), "r"(b), "r"(c));
    return d;
}

// ---------------------------------------------------------------------------
// Binary conv, lane = pixel, L2-CSA popcount, fma-pipe mad reduction.
//   CW = 4 always (36-word block). W0 selects the cin-half/quarter.
//   res = base + SGN*2*s computed as mad chains; per mode:
//   MODE 0: base=-V          -> z; pool min; sign bit -> word
//   MODE 1: base=C0+K  (neg) -> part
//   MODE 2: base=C0+K+part(neg) -> m; relu; pool; bn -> float
//   MODE 3: base=-V-part     -> z; pool min; sign bit
//   MODE 4: base=C0+K+part(neg) -> part
// Grid: x = (NB*H*W/32)/8 blocks of 8 warps, y = COUT/32.
// ---------------------------------------------------------------------------
template <int H, int W, int CINW, int W0, int COUT, bool POOL, int MODE>
__global__ void __launch_bounds__(256) bconv_px(
    const uint32_t* __restrict__ abits, const uint32_t* __restrict__ wbits,
    const int* __restrict__ tab, const float* __restrict__ scale,
    const float* __restrict__ bias, uint32_t* __restrict__ obits,
    int* __restrict__ part, float* __restrict__ ofloat) {
    constexpr int NT = 256;
    constexpr int CW = 4;
    constexpr int CS = (W < 16) ? W : 16;
    constexpr int RS = 32 / CS;
    constexpr int SPI = (H * W) / 32;       // strips per image
    constexpr int WCS = W / CS;             // col-strips per row-group
    constexpr int TPW = 9;                  // uint4 per cout (9 taps x 1)
    constexpr int NPIX = NB * H * W;
    constexpr int C0 = 9 * CW * 32;
    constexpr bool POS = (MODE == 0 || MODE == 3);

    __shared__ uint4 sw4[32 * TPW];
    __shared__ int sk[9 * 33];
    __shared__ float ssc[32], sbi[32];

    const int g = blockIdx.y;
    {
        uint32_t* sws = (uint32_t*)sw4;
        for (int idx = threadIdx.x; idx < 32 * 9 * CW; idx += NT) {
            int c = idx / (9 * CW);
            int t = idx - c * (9 * CW);
            int tap = t / CW, w = t - tap * CW;
            sws[idx] = wbits[((size_t)tap * CINW + W0 + w) * COUT + g * 32 + c];
        }
        for (int idx = threadIdx.x; idx < 9 * 32; idx += NT) {
            int p = idx >> 5, c = idx & 31;
            sk[p * 33 + c] = tab[p * COUT + g * 32 + c];
        }
        if (threadIdx.x < 32) {
            ssc[threadIdx.x] = scale[g * 32 + threadIdx.x];
            sbi[threadIdx.x] = bias[g * 32 + threadIdx.x];
        }
    }
    __syncthreads();

    const int lane = threadIdx.x & 31;
    const int warp = threadIdx.x >> 5;
    const int sid = blockIdx.x * 8 + warp;
    const int n = sid / SPI;
    const int si = sid - n * SPI;
    const int rowg = si / WCS;
    const int colg = si - rowg * WCS;
    const int r = lane / CS;
    const int x = lane - r * CS;
    const int py = rowg * RS + r;
    const int px = colg * CS + x;

    // mad weights (registers; sign folds the mode)
    const int w2v = POS ? 2 : -2;
    const int w4v = POS ? 4 : -4;
    const int w8v = POS ? 8 : -8;

    // Activation patch (zero-filled outside the image)
    uint4 patch[TPW];
#pragma unroll
    for (int ky = 0; ky < 3; ky++) {
#pragma unroll
        for (int kx = 0; kx < 3; kx++) {
            int iy = py + ky - 1, ix = px + kx - 1;
            bool ok = ((unsigned)iy < (unsigned)H) && ((unsigned)ix < (unsigned)W);
            uint4 a = make_uint4(0u, 0u, 0u, 0u);
            if (ok) a = __ldg((const uint4*)(abits +
                    ((size_t)(n * H + iy) * W + ix) * CINW + W0));
            patch[ky * 3 + kx] = a;
        }
    }

    const int ty = (py == 0) ? 0 : ((py == H - 1) ? 2 : 1);
    const int txp = (px == 0) ? 0 : ((px == W - 1) ? 2 : 1);
    const int pat = ty * 3 + txp;
    const int gpix = (n * H + py) * W + px;

    uint32_t word = 0;
#pragma unroll 1
    for (int c = 31; c >= 0; c--) {
        const uint4* wr = &sw4[c * TPW];
        const int dv = sk[pat * 33 + c];
        // XOR 36 words
        uint32_t xw[36];
#pragma unroll
        for (int t = 0; t < 9; t++) {
            uint4 wv = wr[t];              // warp-uniform -> LDS broadcast
            uint4 av = patch[t];
            xw[t * 4 + 0] = av.x ^ wv.x;
            xw[t * 4 + 1] = av.y ^ wv.y;
            xw[t * 4 + 2] = av.z ^ wv.z;
            xw[t * 4 + 3] = av.w ^ wv.w;
        }
        // L1: 36 -> 12 s1 (wt1) + 12 c1 (wt2)
        uint32_t s1[12], c1[12];
#pragma unroll
        for (int i = 0; i < 12; i++)
            csa(xw[3 * i], xw[3 * i + 1], xw[3 * i + 2], s1[i], c1[i]);
        // L2: 12 wt1 -> 4+4; 12 wt2 -> 4+4
        uint32_t s2[4], c2[4], t2[4], d4[4];
#pragma unroll
        for (int i = 0; i < 4; i++)
            csa(s1[3 * i], s1[3 * i + 1], s1[3 * i + 2], s2[i], c2[i]);
#pragma unroll
        for (int i = 0; i < 4; i++)
            csa(c1[3 * i], c1[3 * i + 1], c1[3 * i + 2], t2[i], d4[i]);

        // base per mode (res = base + SGN*2*s)
        int base;
        if constexpr (MODE == 0) {
            base = -dv;
        } else if constexpr (MODE == 1) {
            base = C0 + dv;
        } else if constexpr (MODE == 3) {
            base = -dv - __ldg(part + (size_t)(g * 32 + c) * NPIX + gpix);
        } else {   // MODE 2 / 4
            base = C0 + dv + __ldg(part + (size_t)(g * 32 + c) * NPIX + gpix);
        }
        // two mad chains on the fma pipe
        int a1 = base, a2 = 0;
        a1 = madi(__popc(s2[0]), w2v, a1);
        a1 = madi(__popc(s2[1]), w2v, a1);
        a1 = madi(__popc(s2[2]), w2v, a1);
        a1 = madi(__popc(s2[3]), w2v, a1);
        a1 = madi(__popc(c2[0]), w4v, a1);
        a1 = madi(__popc(c2[1]), w4v, a1);
        a1 = madi(__popc(c2[2]), w4v, a1);
        a1 = madi(__popc(c2[3]), w4v, a1);
        a2 = madi(__popc(t2[0]), w4v, a2);
        a2 = madi(__popc(t2[1]), w4v, a2);
        a2 = madi(__popc(t2[2]), w4v, a2);
        a2 = madi(__popc(t2[3]), w4v, a2);
        a2 = madi(__popc(d4[0]), w8v, a2);
        a2 = madi(__popc(d4[1]), w8v, a2);
        a2 = madi(__popc(d4[2]), w8v, a2);
        a2 = madi(__popc(d4[3]), w8v, a2);
        int res = a1 + a2;

        if constexpr (MODE == 0 || MODE == 3) {
            int z = res;                   // z = T - dot (+ part shift)
            if constexpr (POOL) {
                z = min(z, __shfl_xor_sync(0xffffffffu, z, 1));
                z = min(z, __shfl_xor_sync(0xffffffffu, z, CS));
            }
            word = (word << 1) | ((uint32_t)z >> 31);
        } else if constexpr (MODE == 1 || MODE == 4) {
            part[(size_t)(g * 32 + c) * NPIX + gpix] = res;
        } else {                            // MODE 2: final float
            int m = max(res, 0);           // relu (before pool is exact)
            if constexpr (POOL) {
                m = max(m, __shfl_xor_sync(0xffffffffu, m, 1));
                m = max(m, __shfl_xor_sync(0xffffffffu, m, CS));
            }
            float v = fmaf((float)m, ssc[c], sbi[c]);
            if (((r & 1) == 0) && ((x & 1) == 0)) {
                int opix = (n * (H / 2) + (py >> 1)) * (W / 2) + (px >> 1);
                ofloat[(size_t)opix * COUT + g * 32 + c] = v;
            }
        }
    }

    if constexpr (MODE == 0 || MODE == 3) {
        if constexpr (POOL) {
            if (((r & 1) == 0) && ((x & 1) == 0)) {
                int opix = (n * (H / 2) + (py >> 1)) * (W / 2) + (px >> 1);
                obits[(size_t)opix * (COUT / 32) + g] = word;
            }
        } else {
            obits[(size_t)gpix * (COUT / 32) + g] = word;
        }
    }
}

// ---------------------------------------------------------------------------
// Dense (512->10) + softmax, one warp per output pixel.
// ---------------------------------------------------------------------------
__global__ void dense_softmax_kernel(const float* __restrict__ h, const float* __restrict__ dw,
                                     const float* __restrict__ db, float* __restrict__ out) {
    int warp = (blockIdx.x * blockDim.x + threadIdx.x) >> 5;
    int lane = threadIdx.x & 31;
    if (warp >= NB * 4 * 4) return;
    float acc[10];
#pragma unroll
    for (int j = 0; j < 10; j++) acc[j] = 0.0f;
    const float* hp = h + (size_t)warp * 512;
#pragma unroll
    for (int k = 0; k < 16; k++) {
        int cc = k * 32 + lane;
        float hv = hp[cc];
        const float* wp = dw + cc * 10;
#pragma unroll
        for (int j = 0; j < 10; j++) acc[j] = fmaf(hv, __ldg(wp + j), acc[j]);
    }
#pragma unroll
    for (int s = 16; s > 0; s >>= 1) {
#pragma unroll
        for (int j = 0; j < 10; j++) acc[j] += __shfl_xor_sync(0xffffffffu, acc[j], s);
    }
    if (lane == 0) {
        float l[10], m = -1e30f;
#pragma unroll
        for (int j = 0; j < 10; j++) { l[j] = acc[j] + db[j]; m = fmaxf(m, l[j]); }
        float sum = 0.0f;
#pragma unroll
        for (int j = 0; j < 10; j++) { l[j] = expf(l[j] - m); sum += l[j]; }
        float inv = 1.0f / sum;
#pragma unroll
        for (int j = 0; j < 10; j++) out[warp * 10 + j] = l[j] * inv;
    }
}

// ---------------------------------------------------------------------------
// Launch. Input order: 0:x 1:w1 2:b1 3:w2 4:w3 5:w4 6:w5 7:w6
//  8..19: bn{1..6}_scale/bias interleaved, 20:dense_w 21:dense_b
// ---------------------------------------------------------------------------
extern "C" void kernel_launch(void* const* d_in, const int* in_sizes, int n_in,
                              void* d_out, int out_size) {
    const float* x   = (const float*)d_in[0];
    const float* w1  = (const float*)d_in[1];
    const float* b1  = (const float*)d_in[2];
    const float* w2  = (const float*)d_in[3];
    const float* w3  = (const float*)d_in[4];
    const float* w4  = (const float*)d_in[5];
    const float* w5  = (const float*)d_in[6];
    const float* w6  = (const float*)d_in[7];
    const float* bn1s = (const float*)d_in[8];
    const float* bn1b = (const float*)d_in[9];
    const float* bn2s = (const float*)d_in[10];
    const float* bn2b = (const float*)d_in[11];
    const float* bn3s = (const float*)d_in[12];
    const float* bn3b = (const float*)d_in[13];
    const float* bn4s = (const float*)d_in[14];
    const float* bn4b = (const float*)d_in[15];
    const float* bn5s = (const float*)d_in[16];
    const float* bn5b = (const float*)d_in[17];
    const float* bn6s = (const float*)d_in[18];
    const float* bn6b = (const float*)d_in[19];
    const float* dw   = (const float*)d_in[20];
    const float* db   = (const float*)d_in[21];
    float* out = (float*)d_out;

    uint32_t *bits1, *bits2, *bits3, *bits4, *bits5;
    uint32_t *wb2, *wb3, *wb4, *wb5, *wb6;
    int *V2, *V3, *K4A, *V4B, *K5A, *V5B, *K6A, *K6B, *K6C, *K6D, *part;
    float* h6;
    cudaGetSymbolAddress((void**)&bits1, g_bits1);
    cudaGetSymbolAddress((void**)&bits2, g_bits2);
    cudaGetSymbolAddress((void**)&bits3, g_bits3);
    cudaGetSymbolAddress((void**)&bits4, g_bits4);
    cudaGetSymbolAddress((void**)&bits5, g_bits5);
    cudaGetSymbolAddress((void**)&wb2, g_wb2);
    cudaGetSymbolAddress((void**)&wb3, g_wb3);
    cudaGetSymbolAddress((void**)&wb4, g_wb4);
    cudaGetSymbolAddress((void**)&wb5, g_wb5);
    cudaGetSymbolAddress((void**)&wb6, g_wb6);
    cudaGetSymbolAddress((void**)&V2, g_V2);
    cudaGetSymbolAddress((void**)&V3, g_V3);
    cudaGetSymbolAddress((void**)&K4A, g_K4A);
    cudaGetSymbolAddress((void**)&V4B, g_V4B);
    cudaGetSymbolAddress((void**)&K5A, g_K5A);
    cudaGetSymbolAddress((void**)&V5B, g_V5B);
    cudaGetSymbolAddress((void**)&K6A, g_K6A);
    cudaGetSymbolAddress((void**)&K6B, g_K6B);
    cudaGetSymbolAddress((void**)&K6C, g_K6C);
    cudaGetSymbolAddress((void**)&K6D, g_K6D);
    cudaGetSymbolAddress((void**)&part, g_part);
    cudaGetSymbolAddress((void**)&h6, g_h6);

    // 0: weight packing
    const int npack = 9 * 4 * 128 + 9 * 4 * 256 + 9 * 8 * 256 + 9 * 8 * 512 + 9 * 16 * 512;
    pack_all_kernel<<<(npack + 255) / 256, 256>>>(w2, w3, w4, w5, w6,
                                                  wb2, wb3, wb4, wb5, wb6);
    // 1: V/K tables
    const int nk = 9 * (128 + 256 * 3 + 512 * 6);
    tab_all_kernel<<<(nk + 255) / 256, 256>>>(wb2, wb3, wb4, wb5, wb6,
                                              bn2s, bn2b, bn3s, bn3b,
                                              bn4s, bn4b, bn5s, bn5b,
                                              V2, V3, K4A, V4B, K5A, V5B,
                                              K6A, K6B, K6C, K6D);

    // 2: conv1 + relu + bn1 + binarize   (8 pixels per block)
    conv1_kernel<<<NB * 32 * 32 / 8, 128>>>(x, w1, b1, bn1s, bn1b, bits1);

    // 3: bconv2 (128->128) + pool + bn2
    bconv_px<32, 32, 4, 0, 128, true, 0><<<dim3(512, 4), 256>>>(
        bits1, wb2, V2, bn2s, bn2b, bits2, nullptr, nullptr);
    // 4: bconv3 (128->256) + bn3
    bconv_px<16, 16, 4, 0, 256, false, 0><<<dim3(128, 8), 256>>>(
        bits2, wb3, V3, bn3s, bn3b, bits3, nullptr, nullptr);
    // 5-6: bconv4 (256->256) + pool + bn4, split into 2 cin-halves
    bconv_px<16, 16, 8, 0, 256, false, 1><<<dim3(128, 8), 256>>>(
        bits3, wb4, K4A, bn4s, bn4b, nullptr, part, nullptr);
    bconv_px<16, 16, 8, 4, 256, true, 3><<<dim3(128, 8), 256>>>(
        bits3, wb4, V4B, bn4s, bn4b, bits4, part, nullptr);
    // 7-8: bconv5 (256->512) + bn5, split into 2 cin-halves
    bconv_px<8, 8, 8, 0, 512, false, 1><<<dim3(32, 16), 256>>>(
        bits4, wb5, K5A, bn5s, bn5b, nullptr, part, nullptr);
    bconv_px<8, 8, 8, 4, 512, false, 3><<<dim3(32, 16), 256>>>(
        bits4, wb5, V5B, bn5s, bn5b, bits5, part, nullptr);
    // 9-12: bconv6 (512->512) + pool + bn6 -> float, 4 cin-quarters
    bconv_px<8, 8, 16, 0, 512, false, 1><<<dim3(32, 16), 256>>>(
        bits5, wb6, K6A, bn6s, bn6b, nullptr, part, nullptr);
    bconv_px<8, 8, 16, 4, 512, false, 4><<<dim3(32, 16), 256>>>(
        bits5, wb6, K6B, bn6s, bn6b, nullptr, part, nullptr);
    bconv_px<8, 8, 16, 8, 512, false, 4><<<dim3(32, 16), 256>>>(
        bits5, wb6, K6C, bn6s, bn6b, nullptr, part, nullptr);
    bconv_px<8, 8, 16, 12, 512, true, 2><<<dim3(32, 16), 256>>>(
        bits5, wb6, K6D, bn6s, bn6b, nullptr, part, h6);

    // 13: dense + softmax
    dense_softmax_kernel<<<NB * 4 * 4 * 32 / 256, 256>>>(h6, dw, db, out);
}